// round 3
// baseline (speedup 1.0000x reference)
#include <cuda_runtime.h>
#include <math_constants.h>

#define SS 4096
#define II 1024
#define CC 8
#define HH 8
#define SBLK (SS/32)

typedef unsigned long long u64;

// ---- scratch ----
__device__ float g_k[(size_t)II*SS];
__device__ float g_v[(size_t)II*SS];
__device__ float g_b[(size_t)II*SS];
__device__ float g_qpart[(size_t)SBLK*II*9];
__device__ float g_o[(size_t)II*HH];

// ---- f32x2 helpers ----
__device__ __forceinline__ u64 pk2(float lo, float hi){u64 r;asm("mov.b64 %0,{%1,%2};":"=l"(r):"f"(lo),"f"(hi));return r;}
__device__ __forceinline__ void un2(u64 v, float&a, float&b){asm("mov.b64 {%0,%1},%2;":"=f"(a),"=f"(b):"l"(v));}
__device__ __forceinline__ u64 f2fma(u64 a,u64 b,u64 c){u64 d;asm("fma.rn.f32x2 %0,%1,%2,%3;":"=l"(d):"l"(a),"l"(b),"l"(c));return d;}
__device__ __forceinline__ u64 f2add(u64 a,u64 b){u64 d;asm("add.rn.f32x2 %0,%1,%2;":"=l"(d):"l"(a),"l"(b));return d;}
__device__ __forceinline__ u64 f2mul(u64 a,u64 b){u64 d;asm("mul.rn.f32x2 %0,%1,%2;":"=l"(d):"l"(a),"l"(b));return d;}

// ============================================================
// K1: LayerNorm + k/v/bias (transposed) + q-pool partials
// ============================================================
__global__ __launch_bounds__(256,4) void k1_kernel(
    const float* __restrict__ m, const float* __restrict__ mask,
    const float* __restrict__ gamma, const float* __restrict__ beta,
    const float* __restrict__ Wk, const float* __restrict__ Wv)
{
    __shared__ float tk[32][33], tv[32][33], tb[32][33];
    __shared__ float red[3][8][33];
    __shared__ float wgt[32];
    int tid = threadIdx.x;
    if (tid < 32) {
        float v;
        if      (tid <  8) v = gamma[tid];
        else if (tid < 16) v = beta[tid-8];
        else if (tid < 24) v = Wk[tid-16];
        else               v = Wv[tid-24];
        wgt[tid] = v;
    }
    __syncthreads();

    int il = tid & 31, wp = tid >> 5;
    int i  = blockIdx.x*32 + il;
    int s0 = blockIdx.y*32;

    float qacc[8];
    #pragma unroll
    for (int c = 0; c < 8; c++) qacc[c] = 0.f;
    float macc = 0.f;

    #pragma unroll
    for (int ssl = 0; ssl < 4; ssl++) {
        int sl = wp*4 + ssl;
        int s  = s0 + sl;
        const float4* p = reinterpret_cast<const float4*>(m + ((size_t)s*II + i)*CC);
        float4 a = p[0], b4 = p[1];
        float x[8] = {a.x,a.y,a.z,a.w,b4.x,b4.y,b4.z,b4.w};
        float mu = 0.f;
        #pragma unroll
        for (int c = 0; c < 8; c++) mu += x[c];
        mu *= 0.125f;
        float var = 0.f;
        #pragma unroll
        for (int c = 0; c < 8; c++) { float d = x[c]-mu; var += d*d; }
        var *= 0.125f;
        float rstd = rsqrtf(var + 1e-5f);
        float mk = mask[(size_t)s*II + i];
        float kv = 0.f, vv = 0.f;
        #pragma unroll
        for (int c = 0; c < 8; c++) {
            float mn = (x[c]-mu)*rstd*wgt[c] + wgt[8+c];
            kv += mn*wgt[16+c];
            vv += mn*wgt[24+c];
            qacc[c] += mn*mk;
        }
        macc += mk;
        tk[il][sl] = kv;
        tv[il][sl] = vv;
        tb[il][sl] = 1e9f*(mk - 1.f);
    }
    __syncthreads();

    {
        int ir = tid >> 3, sj = (tid & 7)*4;
        size_t off = (size_t)(blockIdx.x*32 + ir)*SS + s0 + sj;
        *reinterpret_cast<float4*>(g_k + off) =
            make_float4(tk[ir][sj], tk[ir][sj+1], tk[ir][sj+2], tk[ir][sj+3]);
        *reinterpret_cast<float4*>(g_v + off) =
            make_float4(tv[ir][sj], tv[ir][sj+1], tv[ir][sj+2], tv[ir][sj+3]);
        *reinterpret_cast<float4*>(g_b + off) =
            make_float4(tb[ir][sj], tb[ir][sj+1], tb[ir][sj+2], tb[ir][sj+3]);
    }

    #pragma unroll
    for (int r = 0; r < 3; r++) {
        __syncthreads();
        #pragma unroll
        for (int gch = 0; gch < 3; gch++) {
            int c = r*3 + gch;
            red[gch][wp][il] = (c < 8) ? qacc[c] : macc;
        }
        __syncthreads();
        if (wp < 3) {
            int c = r*3 + wp;
            float sum = 0.f;
            #pragma unroll
            for (int w = 0; w < 8; w++) sum += red[wp][w][il];
            g_qpart[((size_t)blockIdx.y*II + i)*9 + c] = sum;
        }
    }
}

// ---------------- block reduction ----------------
__device__ __forceinline__ float warp_sum(float v) {
    #pragma unroll
    for (int o = 16; o; o >>= 1) v += __shfl_xor_sync(0xffffffffu, v, o);
    return v;
}
template<int N>
__device__ __forceinline__ void block_sum(float* vals, float* buf) {
    int lane = threadIdx.x & 31, wp = threadIdx.x >> 5;
    __syncthreads();
    #pragma unroll
    for (int n = 0; n < N; n++) {
        float v = warp_sum(vals[n]);
        if (lane == 0) buf[wp*N + n] = v;
    }
    __syncthreads();
    if (threadIdx.x < N) {
        float r = buf[threadIdx.x];
        #pragma unroll
        for (int w = 1; w < 8; w++) r += buf[w*N + threadIdx.x];
        buf[8*N + threadIdx.x] = r;
    }
    __syncthreads();
    #pragma unroll
    for (int n = 0; n < N; n++) vals[n] = buf[8*N + n];
}

// ============================================================
// K2: per-column q + softmax (no max pass; logits are O(1),
//     masked entries are -1e9 -> exp underflows to 0)
// ============================================================
__global__ __launch_bounds__(256) void k2_kernel(const float* __restrict__ Wq)
{
    __shared__ float buf[9*16];
    __shared__ float swq[64];
    int tid = threadIdx.x;
    int i = blockIdx.x;
    if (tid < 64) swq[tid] = Wq[tid];

    float part[9];
    #pragma unroll
    for (int c = 0; c < 9; c++) part[c] = 0.f;
    if (tid < SBLK) {
        const float* p = g_qpart + ((size_t)tid*II + i)*9;
        #pragma unroll
        for (int c = 0; c < 9; c++) part[c] = p[c];
    }
    block_sum<9>(part, buf);

    float inv = 1.f/(part[8] + 1e-5f);
    float q[8];
    #pragma unroll
    for (int h = 0; h < 8; h++) {
        float s = 0.f;
        #pragma unroll
        for (int c = 0; c < 8; c++) s += (part[c]*inv)*swq[c*8 + h];
        q[h] = s;
    }

    const float* kp = g_k + (size_t)i*SS + tid*16;
    const float* vp = g_v + (size_t)i*SS + tid*16;
    const float* bp = g_b + (size_t)i*SS + tid*16;

    float so[16];
    #pragma unroll
    for (int n = 0; n < 16; n++) so[n] = 0.f;

    #pragma unroll
    for (int g = 0; g < 4; g++) {
        float4 kq = reinterpret_cast<const float4*>(kp)[g];
        float4 vq = reinterpret_cast<const float4*>(vp)[g];
        float4 bq = reinterpret_cast<const float4*>(bp)[g];
        float kk[4] = {kq.x,kq.y,kq.z,kq.w};
        float vv[4] = {vq.x,vq.y,vq.z,vq.w};
        float bb[4] = {bq.x,bq.y,bq.z,bq.w};
        #pragma unroll
        for (int e = 0; e < 4; e++) {
            #pragma unroll
            for (int h = 0; h < 8; h++) {
                float ex = __expf(fmaf(q[h], kk[e], bb[e]));
                so[h]   += ex;
                so[8+h] = fmaf(ex, vv[e], so[8+h]);
            }
        }
    }
    block_sum<16>(so, buf);

    if (tid < 8) g_o[(size_t)i*8 + tid] = so[8+tid] / so[tid];
}

// ============================================================
// K3: gate + output projection, f32x2 packed (2 rows/pair,
//     4 rows/thread), gamma/beta folded, reversed s order.
// ============================================================
__global__ __launch_bounds__(256) void k3_kernel(
    const float* __restrict__ m,
    const float* __restrict__ gamma, const float* __restrict__ beta,
    const float* __restrict__ Wg, const float* __restrict__ bg,
    const float* __restrict__ Wo, const float* __restrict__ bo,
    float* __restrict__ out)
{
    __shared__ ulonglong2 sWG[8][4];  // [h][cpair]: dup gamma*Wg
    __shared__ ulonglong2 sWO[8][4];  // [h][cpair]: dup Wo
    __shared__ u64 sNW[8];            // dup -sum_c gamma_c*Wg[c,h]
    __shared__ u64 sCB[8];            // dup -(beta@Wg[:,h] + bg_h)
    __shared__ u64 sBO[8];            // dup bo_c

    int tid = threadIdx.x;
    if (tid < 32) {
        int h = tid >> 2, cp = tid & 3;
        float w0 = gamma[2*cp]  * Wg[(2*cp)*8 + h];
        float w1 = gamma[2*cp+1]* Wg[(2*cp+1)*8 + h];
        sWG[h][cp] = make_ulonglong2(pk2(w0,w0), pk2(w1,w1));
    } else if (tid < 64) {
        int t = tid - 32; int h = t >> 2, cp = t & 3;
        float w0 = Wo[h*8 + 2*cp], w1 = Wo[h*8 + 2*cp+1];
        sWO[h][cp] = make_ulonglong2(pk2(w0,w0), pk2(w1,w1));
    } else if (tid < 72) {
        int h = tid - 64;
        float ws = 0.f, cb = 0.f;
        #pragma unroll
        for (int c = 0; c < 8; c++) {
            ws += gamma[c]*Wg[c*8+h];
            cb += beta[c] *Wg[c*8+h];
        }
        cb += bg[h];
        sNW[h] = pk2(-ws, -ws);
        sCB[h] = pk2(-cb, -cb);
    } else if (tid < 80) {
        int c = tid - 72;
        sBO[c] = pk2(bo[c], bo[c]);
    }

    int il = tid & 31, wp = tid >> 5;
    int i  = blockIdx.x*32 + il;
    int s0 = (gridDim.y - 1 - blockIdx.y)*32;   // reversed: ride K1's L2 tail
    int sb = s0 + wp*4;

    float oh[8];
    {
        const float4* po = reinterpret_cast<const float4*>(g_o + (size_t)i*8);
        float4 a = po[0], b4 = po[1];
        oh[0]=a.x; oh[1]=a.y; oh[2]=a.z; oh[3]=a.w;
        oh[4]=b4.x; oh[5]=b4.y; oh[6]=b4.z; oh[7]=b4.w;
    }

    // front-batched loads: 4 rows x 2 float4
    float4 A[4][2];
    #pragma unroll
    for (int r = 0; r < 4; r++) {
        const float4* p = reinterpret_cast<const float4*>(m + ((size_t)(sb+r)*II + i)*CC);
        A[r][0] = p[0]; A[r][1] = p[1];
    }
    __syncthreads();

    u64 xp[2][8];
    #pragma unroll
    for (int p = 0; p < 2; p++) {
        const float4& a0 = A[2*p][0];  const float4& b0 = A[2*p][1];
        const float4& a1 = A[2*p+1][0];const float4& b1 = A[2*p+1][1];
        xp[p][0]=pk2(a0.x,a1.x); xp[p][1]=pk2(a0.y,a1.y);
        xp[p][2]=pk2(a0.z,a1.z); xp[p][3]=pk2(a0.w,a1.w);
        xp[p][4]=pk2(b0.x,b1.x); xp[p][5]=pk2(b0.y,b1.y);
        xp[p][6]=pk2(b0.z,b1.z); xp[p][7]=pk2(b0.w,b1.w);
    }

    const u64 k18 = pk2(0.125f, 0.125f);
    const u64 kn1 = pk2(-1.f, -1.f);

    u64 mu2[2], nrstd2[2];
    #pragma unroll
    for (int p = 0; p < 2; p++) {
        u64 s01 = f2add(xp[p][0], xp[p][1]);
        u64 s23 = f2add(xp[p][2], xp[p][3]);
        u64 s45 = f2add(xp[p][4], xp[p][5]);
        u64 s67 = f2add(xp[p][6], xp[p][7]);
        u64 sum = f2add(f2add(s01,s23), f2add(s45,s67));
        u64 mu = f2mul(sum, k18);
        u64 nmu = f2mul(mu, kn1);
        u64 var = 0;
        {
            u64 d = f2add(xp[p][0], nmu); var = f2mul(d, d);
            #pragma unroll
            for (int c = 1; c < 8; c++) { d = f2add(xp[p][c], nmu); var = f2fma(d, d, var); }
        }
        var = f2mul(var, k18);
        float v0, v1; un2(var, v0, v1);
        nrstd2[p] = pk2(-rsqrtf(v0+1e-5f), -rsqrtf(v1+1e-5f));
        mu2[p] = mu;
    }

    u64 acc[2][8];
    #pragma unroll
    for (int p = 0; p < 2; p++)
        #pragma unroll
        for (int c = 0; c < 8; c++) acc[p][c] = sBO[c];

    #pragma unroll
    for (int h = 0; h < 8; h++) {
        ulonglong2 g0 = sWG[h][0], g1 = sWG[h][1], g2 = sWG[h][2], g3 = sWG[h][3];
        ulonglong2 o0 = sWO[h][0], o1 = sWO[h][1], o2 = sWO[h][2], o3 = sWO[h][3];
        u64 nw = sNW[h], cb = sCB[h];
        #pragma unroll
        for (int p = 0; p < 2; p++) {
            u64 dot = f2mul(xp[p][0], g0.x);
            dot = f2fma(xp[p][1], g0.y, dot);
            dot = f2fma(xp[p][2], g1.x, dot);
            dot = f2fma(xp[p][3], g1.y, dot);
            dot = f2fma(xp[p][4], g2.x, dot);
            dot = f2fma(xp[p][5], g2.y, dot);
            dot = f2fma(xp[p][6], g3.x, dot);
            dot = f2fma(xp[p][7], g3.y, dot);
            u64 t  = f2fma(mu2[p], nw, dot);       // dot - mu*wsum
            u64 zn = f2fma(nrstd2[p], t, cb);      // -(rstd*t + cbias) = -z
            float z0, z1; un2(zn, z0, z1);
            float t0 = __fdividef(oh[h], 1.f + __expf(z0));
            float t1 = __fdividef(oh[h], 1.f + __expf(z1));
            u64 th = pk2(t0, t1);
            acc[p][0] = f2fma(th, o0.x, acc[p][0]);
            acc[p][1] = f2fma(th, o0.y, acc[p][1]);
            acc[p][2] = f2fma(th, o1.x, acc[p][2]);
            acc[p][3] = f2fma(th, o1.y, acc[p][3]);
            acc[p][4] = f2fma(th, o2.x, acc[p][4]);
            acc[p][5] = f2fma(th, o2.y, acc[p][5]);
            acc[p][6] = f2fma(th, o3.x, acc[p][6]);
            acc[p][7] = f2fma(th, o3.y, acc[p][7]);
        }
    }

    #pragma unroll
    for (int p = 0; p < 2; p++) {
        float y0[8], y1[8];
        #pragma unroll
        for (int c = 0; c < 8; c++) un2(acc[p][c], y0[c], y1[c]);
        size_t off0 = ((size_t)(sb+2*p)*II + i)*CC;
        size_t off1 = ((size_t)(sb+2*p+1)*II + i)*CC;
        *reinterpret_cast<float4*>(out + off0)     = make_float4(y0[0],y0[1],y0[2],y0[3]);
        *reinterpret_cast<float4*>(out + off0 + 4) = make_float4(y0[4],y0[5],y0[6],y0[7]);
        *reinterpret_cast<float4*>(out + off1)     = make_float4(y1[0],y1[1],y1[2],y1[3]);
        *reinterpret_cast<float4*>(out + off1 + 4) = make_float4(y1[4],y1[5],y1[6],y1[7]);
    }
}

// ============================================================
extern "C" void kernel_launch(void* const* d_in, const int* in_sizes, int n_in,
                              void* d_out, int out_size)
{
    const float* m     = (const float*)d_in[0];
    const float* mask  = (const float*)d_in[1];
    const float* gamma = (const float*)d_in[2];
    const float* beta  = (const float*)d_in[3];
    const float* Wq    = (const float*)d_in[4];
    const float* Wk    = (const float*)d_in[5];
    const float* Wv    = (const float*)d_in[6];
    const float* Wg    = (const float*)d_in[7];
    const float* bg    = (const float*)d_in[8];
    const float* Wo    = (const float*)d_in[9];
    const float* bo    = (const float*)d_in[10];
    float* out = (float*)d_out;

    dim3 g1(II/32, SS/32);
    k1_kernel<<<g1, 256>>>(m, mask, gamma, beta, Wk, Wv);
    k2_kernel<<<II, 256>>>(Wq);
    dim3 g3(II/32, SS/32);
    k3_kernel<<<g3, 256>>>(m, gamma, beta, Wg, bg, Wo, bo, out);
}

// round 4
// speedup vs baseline: 1.1136x; 1.1136x over previous
#include <cuda_runtime.h>
#include <cuda_fp16.h>
#include <math_constants.h>

#define SS 4096
#define II 1024
#define CC 8
#define HH 8
#define SBLK (SS/32)

typedef unsigned long long u64;

// ---- scratch ----
__device__ __half2 g_kw[(size_t)II*SS];       // (k, w=exp(bias)) per [i][s]
__device__ float   g_v [(size_t)II*SS];       // v [i][s]
__device__ float   g_qpart[(size_t)SBLK*II*9];
__device__ float   g_o[(size_t)II*HH];

// ---- f32x2 helpers ----
__device__ __forceinline__ u64 pk2(float lo, float hi){u64 r;asm("mov.b64 %0,{%1,%2};":"=l"(r):"f"(lo),"f"(hi));return r;}
__device__ __forceinline__ void un2(u64 v, float&a, float&b){asm("mov.b64 {%0,%1},%2;":"=f"(a),"=f"(b):"l"(v));}
__device__ __forceinline__ u64 f2fma(u64 a,u64 b,u64 c){u64 d;asm("fma.rn.f32x2 %0,%1,%2,%3;":"=l"(d):"l"(a),"l"(b),"l"(c));return d;}
__device__ __forceinline__ u64 f2add(u64 a,u64 b){u64 d;asm("add.rn.f32x2 %0,%1,%2;":"=l"(d):"l"(a),"l"(b));return d;}
__device__ __forceinline__ u64 f2mul(u64 a,u64 b){u64 d;asm("mul.rn.f32x2 %0,%1,%2;":"=l"(d):"l"(a),"l"(b));return d;}

// ============================================================
// K1: LayerNorm + (k,w) half2 + v planes (transposed) + q-pool partials
// grid (II/32, SS/32), block 256
// ============================================================
__global__ __launch_bounds__(256) void k1_kernel(
    const float* __restrict__ m, const float* __restrict__ mask,
    const float* __restrict__ gamma, const float* __restrict__ beta,
    const float* __restrict__ Wk, const float* __restrict__ Wv)
{
    __shared__ float tk[32][33], tv[32][33], tw[32][33];
    __shared__ float red[3][8][33];
    __shared__ float wgt[32];
    int tid = threadIdx.x;
    if (tid < 32) {
        float v;
        if      (tid <  8) v = gamma[tid];
        else if (tid < 16) v = beta[tid-8];
        else if (tid < 24) v = Wk[tid-16];
        else               v = Wv[tid-24];
        wgt[tid] = v;
    }
    __syncthreads();

    int il = tid & 31, wp = tid >> 5;
    int i  = blockIdx.x*32 + il;
    int s0 = blockIdx.y*32;

    float qacc[8];
    #pragma unroll
    for (int c = 0; c < 8; c++) qacc[c] = 0.f;
    float macc = 0.f;

    #pragma unroll
    for (int ssl = 0; ssl < 4; ssl++) {
        int sl = wp*4 + ssl;
        int s  = s0 + sl;
        const float4* p = reinterpret_cast<const float4*>(m + ((size_t)s*II + i)*CC);
        float4 a = p[0], b4 = p[1];
        float x[8] = {a.x,a.y,a.z,a.w,b4.x,b4.y,b4.z,b4.w};
        float mu = 0.f;
        #pragma unroll
        for (int c = 0; c < 8; c++) mu += x[c];
        mu *= 0.125f;
        float var = 0.f;
        #pragma unroll
        for (int c = 0; c < 8; c++) { float d = x[c]-mu; var += d*d; }
        var *= 0.125f;
        float rstd = rsqrtf(var + 1e-5f);
        float mk = mask[(size_t)s*II + i];
        float kv = 0.f, vv = 0.f;
        #pragma unroll
        for (int c = 0; c < 8; c++) {
            float mn = (x[c]-mu)*rstd*wgt[c] + wgt[8+c];
            kv += mn*wgt[16+c];
            vv += mn*wgt[24+c];
            qacc[c] += mn*mk;
        }
        macc += mk;
        tk[il][sl] = kv;
        tv[il][sl] = vv;
        tw[il][sl] = __expf(1e9f*(mk - 1.f));   // mk=1 -> 1, mk=0 -> 0
    }
    __syncthreads();

    // coalesced transposed writeout
    {
        int ir = tid >> 3, sj = (tid & 7)*4;
        size_t off = (size_t)(blockIdx.x*32 + ir)*SS + s0 + sj;
        *reinterpret_cast<float4*>(g_v + off) =
            make_float4(tv[ir][sj], tv[ir][sj+1], tv[ir][sj+2], tv[ir][sj+3]);
        __half2 h0 = __floats2half2_rn(tk[ir][sj],   tw[ir][sj]);
        __half2 h1 = __floats2half2_rn(tk[ir][sj+1], tw[ir][sj+1]);
        __half2 h2 = __floats2half2_rn(tk[ir][sj+2], tw[ir][sj+2]);
        __half2 h3 = __floats2half2_rn(tk[ir][sj+3], tw[ir][sj+3]);
        uint4 u;
        u.x = *reinterpret_cast<unsigned int*>(&h0);
        u.y = *reinterpret_cast<unsigned int*>(&h1);
        u.z = *reinterpret_cast<unsigned int*>(&h2);
        u.w = *reinterpret_cast<unsigned int*>(&h3);
        *reinterpret_cast<uint4*>(g_kw + off) = u;
    }

    #pragma unroll
    for (int r = 0; r < 3; r++) {
        __syncthreads();
        #pragma unroll
        for (int gch = 0; gch < 3; gch++) {
            int c = r*3 + gch;
            red[gch][wp][il] = (c < 8) ? qacc[c] : macc;
        }
        __syncthreads();
        if (wp < 3) {
            int c = r*3 + wp;
            float sum = 0.f;
            #pragma unroll
            for (int w = 0; w < 8; w++) sum += red[wp][w][il];
            g_qpart[((size_t)blockIdx.y*II + i)*9 + c] = sum;
        }
    }
}

// ---------------- block reduction ----------------
__device__ __forceinline__ float warp_sum(float v) {
    #pragma unroll
    for (int o = 16; o; o >>= 1) v += __shfl_xor_sync(0xffffffffu, v, o);
    return v;
}
template<int N>
__device__ __forceinline__ void block_sum(float* vals, float* buf) {
    int lane = threadIdx.x & 31, wp = threadIdx.x >> 5;
    __syncthreads();
    #pragma unroll
    for (int n = 0; n < N; n++) {
        float v = warp_sum(vals[n]);
        if (lane == 0) buf[wp*N + n] = v;
    }
    __syncthreads();
    if (threadIdx.x < N) {
        float r = buf[threadIdx.x];
        #pragma unroll
        for (int w = 1; w < 8; w++) r += buf[w*N + threadIdx.x];
        buf[8*N + threadIdx.x] = r;
    }
    __syncthreads();
    #pragma unroll
    for (int n = 0; n < N; n++) vals[n] = buf[8*N + n];
}

// ============================================================
// K2: per-column q + softmax over s (w-folded bias, no max pass)
// grid 1024, block 256
// ============================================================
__global__ __launch_bounds__(256) void k2_kernel(const float* __restrict__ Wq)
{
    __shared__ float buf[9*16];
    __shared__ float swq[64];
    int tid = threadIdx.x;
    int i = blockIdx.x;
    if (tid < 64) swq[tid] = Wq[tid];

    float part[9];
    #pragma unroll
    for (int c = 0; c < 9; c++) part[c] = 0.f;
    if (tid < SBLK) {
        const float* p = g_qpart + ((size_t)tid*II + i)*9;
        #pragma unroll
        for (int c = 0; c < 9; c++) part[c] = p[c];
    }
    block_sum<9>(part, buf);

    float inv = 1.f/(part[8] + 1e-5f);
    float q[8];
    #pragma unroll
    for (int h = 0; h < 8; h++) {
        float s = 0.f;
        #pragma unroll
        for (int c = 0; c < 8; c++) s += (part[c]*inv)*swq[c*8 + h];
        q[h] = s;
    }

    const __half2* kwp = g_kw + (size_t)i*SS + tid*16;
    const float*   vp  = g_v  + (size_t)i*SS + tid*16;

    float so[16];
    #pragma unroll
    for (int n = 0; n < 16; n++) so[n] = 0.f;

    #pragma unroll
    for (int g = 0; g < 4; g++) {
        uint4 kw4 = reinterpret_cast<const uint4*>(kwp)[g];
        float4 vq = reinterpret_cast<const float4*>(vp)[g];
        unsigned kwu[4] = {kw4.x, kw4.y, kw4.z, kw4.w};
        float vv[4] = {vq.x, vq.y, vq.z, vq.w};
        #pragma unroll
        for (int e = 0; e < 4; e++) {
            float2 kw = __half22float2(*reinterpret_cast<__half2*>(&kwu[e]));
            float kk = kw.x, w = kw.y;
            #pragma unroll
            for (int h = 0; h < 8; h++) {
                float ex = w * __expf(q[h]*kk);
                so[h]   += ex;
                so[8+h] = fmaf(ex, vv[e], so[8+h]);
            }
        }
    }
    block_sum<16>(so, buf);

    if (tid < 8) g_o[(size_t)i*8 + tid] = so[8+tid] / so[tid];
}

// ============================================================
// K3: gate + output projection, f32x2 packed, gamma/beta folded
// ============================================================
__global__ __launch_bounds__(256) void k3_kernel(
    const float* __restrict__ m,
    const float* __restrict__ gamma, const float* __restrict__ beta,
    const float* __restrict__ Wg, const float* __restrict__ bg,
    const float* __restrict__ Wo, const float* __restrict__ bo,
    float* __restrict__ out)
{
    __shared__ ulonglong2 sWG[8][4];
    __shared__ ulonglong2 sWO[8][4];
    __shared__ u64 sNW[8];
    __shared__ u64 sCB[8];
    __shared__ u64 sBO[8];

    int tid = threadIdx.x;
    if (tid < 32) {
        int h = tid >> 2, cp = tid & 3;
        float w0 = gamma[2*cp]  * Wg[(2*cp)*8 + h];
        float w1 = gamma[2*cp+1]* Wg[(2*cp+1)*8 + h];
        sWG[h][cp] = make_ulonglong2(pk2(w0,w0), pk2(w1,w1));
    } else if (tid < 64) {
        int t = tid - 32; int h = t >> 2, cp = t & 3;
        float w0 = Wo[h*8 + 2*cp], w1 = Wo[h*8 + 2*cp+1];
        sWO[h][cp] = make_ulonglong2(pk2(w0,w0), pk2(w1,w1));
    } else if (tid < 72) {
        int h = tid - 64;
        float ws = 0.f, cb = 0.f;
        #pragma unroll
        for (int c = 0; c < 8; c++) {
            ws += gamma[c]*Wg[c*8+h];
            cb += beta[c] *Wg[c*8+h];
        }
        cb += bg[h];
        sNW[h] = pk2(-ws, -ws);
        sCB[h] = pk2(-cb, -cb);
    } else if (tid < 80) {
        int c = tid - 72;
        sBO[c] = pk2(bo[c], bo[c]);
    }

    int il = tid & 31, wp = tid >> 5;
    int i  = blockIdx.x*32 + il;
    int s0 = (gridDim.y - 1 - blockIdx.y)*32;
    int sb = s0 + wp*4;

    float oh[8];
    {
        const float4* po = reinterpret_cast<const float4*>(g_o + (size_t)i*8);
        float4 a = po[0], b4 = po[1];
        oh[0]=a.x; oh[1]=a.y; oh[2]=a.z; oh[3]=a.w;
        oh[4]=b4.x; oh[5]=b4.y; oh[6]=b4.z; oh[7]=b4.w;
    }

    float4 A[4][2];
    #pragma unroll
    for (int r = 0; r < 4; r++) {
        const float4* p = reinterpret_cast<const float4*>(m + ((size_t)(sb+r)*II + i)*CC);
        A[r][0] = p[0]; A[r][1] = p[1];
    }
    __syncthreads();

    u64 xp[2][8];
    #pragma unroll
    for (int p = 0; p < 2; p++) {
        const float4& a0 = A[2*p][0];  const float4& b0 = A[2*p][1];
        const float4& a1 = A[2*p+1][0];const float4& b1 = A[2*p+1][1];
        xp[p][0]=pk2(a0.x,a1.x); xp[p][1]=pk2(a0.y,a1.y);
        xp[p][2]=pk2(a0.z,a1.z); xp[p][3]=pk2(a0.w,a1.w);
        xp[p][4]=pk2(b0.x,b1.x); xp[p][5]=pk2(b0.y,b1.y);
        xp[p][6]=pk2(b0.z,b1.z); xp[p][7]=pk2(b0.w,b1.w);
    }

    const u64 k18 = pk2(0.125f, 0.125f);
    const u64 kn1 = pk2(-1.f, -1.f);

    u64 mu2[2], nrstd2[2];
    #pragma unroll
    for (int p = 0; p < 2; p++) {
        u64 s01 = f2add(xp[p][0], xp[p][1]);
        u64 s23 = f2add(xp[p][2], xp[p][3]);
        u64 s45 = f2add(xp[p][4], xp[p][5]);
        u64 s67 = f2add(xp[p][6], xp[p][7]);
        u64 sum = f2add(f2add(s01,s23), f2add(s45,s67));
        u64 mu = f2mul(sum, k18);
        u64 nmu = f2mul(mu, kn1);
        u64 var = 0;
        {
            u64 d = f2add(xp[p][0], nmu); var = f2mul(d, d);
            #pragma unroll
            for (int c = 1; c < 8; c++) { d = f2add(xp[p][c], nmu); var = f2fma(d, d, var); }
        }
        var = f2mul(var, k18);
        float v0, v1; un2(var, v0, v1);
        nrstd2[p] = pk2(-rsqrtf(v0+1e-5f), -rsqrtf(v1+1e-5f));
        mu2[p] = mu;
    }

    u64 acc[2][8];
    #pragma unroll
    for (int p = 0; p < 2; p++)
        #pragma unroll
        for (int c = 0; c < 8; c++) acc[p][c] = sBO[c];

    #pragma unroll
    for (int h = 0; h < 8; h++) {
        ulonglong2 g0 = sWG[h][0], g1 = sWG[h][1], g2 = sWG[h][2], g3 = sWG[h][3];
        ulonglong2 o0 = sWO[h][0], o1 = sWO[h][1], o2 = sWO[h][2], o3 = sWO[h][3];
        u64 nw = sNW[h], cb = sCB[h];
        #pragma unroll
        for (int p = 0; p < 2; p++) {
            u64 dot = f2mul(xp[p][0], g0.x);
            dot = f2fma(xp[p][1], g0.y, dot);
            dot = f2fma(xp[p][2], g1.x, dot);
            dot = f2fma(xp[p][3], g1.y, dot);
            dot = f2fma(xp[p][4], g2.x, dot);
            dot = f2fma(xp[p][5], g2.y, dot);
            dot = f2fma(xp[p][6], g3.x, dot);
            dot = f2fma(xp[p][7], g3.y, dot);
            u64 t  = f2fma(mu2[p], nw, dot);
            u64 zn = f2fma(nrstd2[p], t, cb);
            float z0, z1; un2(zn, z0, z1);
            float t0 = __fdividef(oh[h], 1.f + __expf(z0));
            float t1 = __fdividef(oh[h], 1.f + __expf(z1));
            u64 th = pk2(t0, t1);
            acc[p][0] = f2fma(th, o0.x, acc[p][0]);
            acc[p][1] = f2fma(th, o0.y, acc[p][1]);
            acc[p][2] = f2fma(th, o1.x, acc[p][2]);
            acc[p][3] = f2fma(th, o1.y, acc[p][3]);
            acc[p][4] = f2fma(th, o2.x, acc[p][4]);
            acc[p][5] = f2fma(th, o2.y, acc[p][5]);
            acc[p][6] = f2fma(th, o3.x, acc[p][6]);
            acc[p][7] = f2fma(th, o3.y, acc[p][7]);
        }
    }

    #pragma unroll
    for (int p = 0; p < 2; p++) {
        float y0[8], y1[8];
        #pragma unroll
        for (int c = 0; c < 8; c++) un2(acc[p][c], y0[c], y1[c]);
        size_t off0 = ((size_t)(sb+2*p)*II + i)*CC;
        size_t off1 = ((size_t)(sb+2*p+1)*II + i)*CC;
        *reinterpret_cast<float4*>(out + off0)     = make_float4(y0[0],y0[1],y0[2],y0[3]);
        *reinterpret_cast<float4*>(out + off0 + 4) = make_float4(y0[4],y0[5],y0[6],y0[7]);
        *reinterpret_cast<float4*>(out + off1)     = make_float4(y1[0],y1[1],y1[2],y1[3]);
        *reinterpret_cast<float4*>(out + off1 + 4) = make_float4(y1[4],y1[5],y1[6],y1[7]);
    }
}

// ============================================================
extern "C" void kernel_launch(void* const* d_in, const int* in_sizes, int n_in,
                              void* d_out, int out_size)
{
    const float* m     = (const float*)d_in[0];
    const float* mask  = (const float*)d_in[1];
    const float* gamma = (const float*)d_in[2];
    const float* beta  = (const float*)d_in[3];
    const float* Wq    = (const float*)d_in[4];
    const float* Wk    = (const float*)d_in[5];
    const float* Wv    = (const float*)d_in[6];
    const float* Wg    = (const float*)d_in[7];
    const float* bg    = (const float*)d_in[8];
    const float* Wo    = (const float*)d_in[9];
    const float* bo    = (const float*)d_in[10];
    float* out = (float*)d_out;

    dim3 g1(II/32, SS/32);
    k1_kernel<<<g1, 256>>>(m, mask, gamma, beta, Wk, Wv);
    k2_kernel<<<II, 256>>>(Wq);
    dim3 g3(II/32, SS/32);
    k3_kernel<<<g3, 256>>>(m, gamma, beta, Wg, bg, Wo, bo, out);
}

// round 5
// speedup vs baseline: 1.1560x; 1.0380x over previous
#include <cuda_runtime.h>
#include <cuda_fp16.h>
#include <math_constants.h>

#define SS 4096
#define II 1024
#define CC 8
#define HH 8
#define SBLK (SS/32)

typedef unsigned long long u64;

// ---- scratch ----
__device__ __half2 g_kw[(size_t)II*SS];       // (k, w=exp(bias)) per [i][s]
__device__ float   g_v [(size_t)II*SS];       // v [i][s]
__device__ float   g_qpart[(size_t)SBLK*II*9];
__device__ float   g_o[(size_t)II*HH];

// ---- f32x2 helpers ----
__device__ __forceinline__ u64 pk2(float lo, float hi){u64 r;asm("mov.b64 %0,{%1,%2};":"=l"(r):"f"(lo),"f"(hi));return r;}
__device__ __forceinline__ void un2(u64 v, float&a, float&b){asm("mov.b64 {%0,%1},%2;":"=f"(a),"=f"(b):"l"(v));}
__device__ __forceinline__ u64 f2fma(u64 a,u64 b,u64 c){u64 d;asm("fma.rn.f32x2 %0,%1,%2,%3;":"=l"(d):"l"(a),"l"(b),"l"(c));return d;}
__device__ __forceinline__ u64 f2add(u64 a,u64 b){u64 d;asm("add.rn.f32x2 %0,%1,%2;":"=l"(d):"l"(a),"l"(b));return d;}
__device__ __forceinline__ u64 f2mul(u64 a,u64 b){u64 d;asm("mul.rn.f32x2 %0,%1,%2;":"=l"(d):"l"(a),"l"(b));return d;}

// ============================================================
// K1: LayerNorm + (k,w) half2 + v planes (transposed) + q-pool partials
// grid (II/32, SS/32), block 256. Scratch stores are evict-first (.cs)
// so the streamed m stays L2-resident for K3.
// ============================================================
__global__ __launch_bounds__(256,3) void k1_kernel(
    const float* __restrict__ m, const float* __restrict__ mask,
    const float* __restrict__ gamma, const float* __restrict__ beta,
    const float* __restrict__ Wk, const float* __restrict__ Wv)
{
    __shared__ float tk[32][33], tv[32][33], tw[32][33];
    __shared__ float red[3][8][33];
    __shared__ float wgt[32];
    int tid = threadIdx.x;
    if (tid < 32) {
        float v;
        if      (tid <  8) v = gamma[tid];
        else if (tid < 16) v = beta[tid-8];
        else if (tid < 24) v = Wk[tid-16];
        else               v = Wv[tid-24];
        wgt[tid] = v;
    }
    __syncthreads();

    int il = tid & 31, wp = tid >> 5;
    int i  = blockIdx.x*32 + il;
    int s0 = blockIdx.y*32;
    int sb = s0 + wp*4;

    // front-batched loads: maximize MLP before any math
    float4 A[4][2];
    float mk[4];
    #pragma unroll
    for (int r = 0; r < 4; r++) {
        const float4* p = reinterpret_cast<const float4*>(m + ((size_t)(sb+r)*II + i)*CC);
        A[r][0] = p[0]; A[r][1] = p[1];
    }
    #pragma unroll
    for (int r = 0; r < 4; r++) mk[r] = mask[(size_t)(sb+r)*II + i];

    float qacc[8];
    #pragma unroll
    for (int c = 0; c < 8; c++) qacc[c] = 0.f;
    float macc = 0.f;

    #pragma unroll
    for (int r = 0; r < 4; r++) {
        int sl = wp*4 + r;
        float x[8] = {A[r][0].x,A[r][0].y,A[r][0].z,A[r][0].w,
                      A[r][1].x,A[r][1].y,A[r][1].z,A[r][1].w};
        float mu = 0.f;
        #pragma unroll
        for (int c = 0; c < 8; c++) mu += x[c];
        mu *= 0.125f;
        float var = 0.f;
        #pragma unroll
        for (int c = 0; c < 8; c++) { float d = x[c]-mu; var += d*d; }
        var *= 0.125f;
        float rstd = rsqrtf(var + 1e-5f);
        float kv = 0.f, vv = 0.f;
        #pragma unroll
        for (int c = 0; c < 8; c++) {
            float mn = (x[c]-mu)*rstd*wgt[c] + wgt[8+c];
            kv += mn*wgt[16+c];
            vv += mn*wgt[24+c];
            qacc[c] += mn*mk[r];
        }
        macc += mk[r];
        tk[il][sl] = kv;
        tv[il][sl] = vv;
        tw[il][sl] = __expf(1e9f*(mk[r] - 1.f));
    }
    __syncthreads();

    // coalesced transposed writeout, evict-first
    {
        int ir = tid >> 3, sj = (tid & 7)*4;
        size_t off = (size_t)(blockIdx.x*32 + ir)*SS + s0 + sj;
        __stcs(reinterpret_cast<float4*>(g_v + off),
               make_float4(tv[ir][sj], tv[ir][sj+1], tv[ir][sj+2], tv[ir][sj+3]));
        __half2 h0 = __floats2half2_rn(tk[ir][sj],   tw[ir][sj]);
        __half2 h1 = __floats2half2_rn(tk[ir][sj+1], tw[ir][sj+1]);
        __half2 h2 = __floats2half2_rn(tk[ir][sj+2], tw[ir][sj+2]);
        __half2 h3 = __floats2half2_rn(tk[ir][sj+3], tw[ir][sj+3]);
        uint4 u;
        u.x = *reinterpret_cast<unsigned int*>(&h0);
        u.y = *reinterpret_cast<unsigned int*>(&h1);
        u.z = *reinterpret_cast<unsigned int*>(&h2);
        u.w = *reinterpret_cast<unsigned int*>(&h3);
        __stcs(reinterpret_cast<uint4*>(g_kw + off), u);
    }

    #pragma unroll
    for (int r = 0; r < 3; r++) {
        __syncthreads();
        #pragma unroll
        for (int gch = 0; gch < 3; gch++) {
            int c = r*3 + gch;
            red[gch][wp][il] = (c < 8) ? qacc[c] : macc;
        }
        __syncthreads();
        if (wp < 3) {
            int c = r*3 + wp;
            float sum = 0.f;
            #pragma unroll
            for (int w = 0; w < 8; w++) sum += red[wp][w][il];
            __stcs(&g_qpart[((size_t)blockIdx.y*II + i)*9 + c], sum);
        }
    }
}

// ---------------- block reduction ----------------
__device__ __forceinline__ float warp_sum(float v) {
    #pragma unroll
    for (int o = 16; o; o >>= 1) v += __shfl_xor_sync(0xffffffffu, v, o);
    return v;
}
template<int N>
__device__ __forceinline__ void block_sum(float* vals, float* buf) {
    int lane = threadIdx.x & 31, wp = threadIdx.x >> 5;
    __syncthreads();
    #pragma unroll
    for (int n = 0; n < N; n++) {
        float v = warp_sum(vals[n]);
        if (lane == 0) buf[wp*N + n] = v;
    }
    __syncthreads();
    if (threadIdx.x < N) {
        float r = buf[threadIdx.x];
        #pragma unroll
        for (int w = 1; w < 8; w++) r += buf[w*N + threadIdx.x];
        buf[8*N + threadIdx.x] = r;
    }
    __syncthreads();
    #pragma unroll
    for (int n = 0; n < N; n++) vals[n] = buf[8*N + n];
}

// ============================================================
// K2: per-column q + softmax over s. Scratch reads are .cs
// (dead after this kernel) to protect m's L2 footprint.
// ============================================================
__global__ __launch_bounds__(256) void k2_kernel(const float* __restrict__ Wq)
{
    __shared__ float buf[9*16];
    __shared__ float swq[64];
    int tid = threadIdx.x;
    int i = blockIdx.x;
    if (tid < 64) swq[tid] = Wq[tid];

    float part[9];
    #pragma unroll
    for (int c = 0; c < 9; c++) part[c] = 0.f;
    if (tid < SBLK) {
        const float* p = g_qpart + ((size_t)tid*II + i)*9;
        #pragma unroll
        for (int c = 0; c < 9; c++) part[c] = __ldcs(p + c);
    }
    block_sum<9>(part, buf);

    float inv = 1.f/(part[8] + 1e-5f);
    float q[8];
    #pragma unroll
    for (int h = 0; h < 8; h++) {
        float s = 0.f;
        #pragma unroll
        for (int c = 0; c < 8; c++) s += (part[c]*inv)*swq[c*8 + h];
        q[h] = s;
    }

    const __half2* kwp = g_kw + (size_t)i*SS + tid*16;
    const float*   vp  = g_v  + (size_t)i*SS + tid*16;

    float so[16];
    #pragma unroll
    for (int n = 0; n < 16; n++) so[n] = 0.f;

    #pragma unroll
    for (int g = 0; g < 4; g++) {
        uint4 kw4 = __ldcs(reinterpret_cast<const uint4*>(kwp) + g);
        float4 vq = __ldcs(reinterpret_cast<const float4*>(vp) + g);
        unsigned kwu[4] = {kw4.x, kw4.y, kw4.z, kw4.w};
        float vv[4] = {vq.x, vq.y, vq.z, vq.w};
        #pragma unroll
        for (int e = 0; e < 4; e++) {
            float2 kw = __half22float2(*reinterpret_cast<__half2*>(&kwu[e]));
            float kk = kw.x, w = kw.y;
            #pragma unroll
            for (int h = 0; h < 8; h++) {
                float ex = w * __expf(q[h]*kk);
                so[h]   += ex;
                so[8+h] = fmaf(ex, vv[e], so[8+h]);
            }
        }
    }
    block_sum<16>(so, buf);

    if (tid < 8) g_o[(size_t)i*8 + tid] = so[8+tid] / so[tid];
}

// ============================================================
// K3: gate + output projection, f32x2 packed, gamma/beta folded.
// Reads m tail-first (L2-resident from K1); out stores evict-first.
// ============================================================
__global__ __launch_bounds__(256) void k3_kernel(
    const float* __restrict__ m,
    const float* __restrict__ gamma, const float* __restrict__ beta,
    const float* __restrict__ Wg, const float* __restrict__ bg,
    const float* __restrict__ Wo, const float* __restrict__ bo,
    float* __restrict__ out)
{
    __shared__ ulonglong2 sWG[8][4];
    __shared__ ulonglong2 sWO[8][4];
    __shared__ u64 sNW[8];
    __shared__ u64 sCB[8];
    __shared__ u64 sBO[8];

    int tid = threadIdx.x;
    if (tid < 32) {
        int h = tid >> 2, cp = tid & 3;
        float w0 = gamma[2*cp]  * Wg[(2*cp)*8 + h];
        float w1 = gamma[2*cp+1]* Wg[(2*cp+1)*8 + h];
        sWG[h][cp] = make_ulonglong2(pk2(w0,w0), pk2(w1,w1));
    } else if (tid < 64) {
        int t = tid - 32; int h = t >> 2, cp = t & 3;
        float w0 = Wo[h*8 + 2*cp], w1 = Wo[h*8 + 2*cp+1];
        sWO[h][cp] = make_ulonglong2(pk2(w0,w0), pk2(w1,w1));
    } else if (tid < 72) {
        int h = tid - 64;
        float ws = 0.f, cb = 0.f;
        #pragma unroll
        for (int c = 0; c < 8; c++) {
            ws += gamma[c]*Wg[c*8+h];
            cb += beta[c] *Wg[c*8+h];
        }
        cb += bg[h];
        sNW[h] = pk2(-ws, -ws);
        sCB[h] = pk2(-cb, -cb);
    } else if (tid < 80) {
        int c = tid - 72;
        sBO[c] = pk2(bo[c], bo[c]);
    }

    int il = tid & 31, wp = tid >> 5;
    int i  = blockIdx.x*32 + il;
    int s0 = (gridDim.y - 1 - blockIdx.y)*32;
    int sb = s0 + wp*4;

    float oh[8];
    {
        const float4* po = reinterpret_cast<const float4*>(g_o + (size_t)i*8);
        float4 a = po[0], b4 = po[1];
        oh[0]=a.x; oh[1]=a.y; oh[2]=a.z; oh[3]=a.w;
        oh[4]=b4.x; oh[5]=b4.y; oh[6]=b4.z; oh[7]=b4.w;
    }

    float4 A[4][2];
    #pragma unroll
    for (int r = 0; r < 4; r++) {
        const float4* p = reinterpret_cast<const float4*>(m + ((size_t)(sb+r)*II + i)*CC);
        A[r][0] = p[0]; A[r][1] = p[1];
    }
    __syncthreads();

    u64 xp[2][8];
    #pragma unroll
    for (int p = 0; p < 2; p++) {
        const float4& a0 = A[2*p][0];  const float4& b0 = A[2*p][1];
        const float4& a1 = A[2*p+1][0];const float4& b1 = A[2*p+1][1];
        xp[p][0]=pk2(a0.x,a1.x); xp[p][1]=pk2(a0.y,a1.y);
        xp[p][2]=pk2(a0.z,a1.z); xp[p][3]=pk2(a0.w,a1.w);
        xp[p][4]=pk2(b0.x,b1.x); xp[p][5]=pk2(b0.y,b1.y);
        xp[p][6]=pk2(b0.z,b1.z); xp[p][7]=pk2(b0.w,b1.w);
    }

    const u64 k18 = pk2(0.125f, 0.125f);
    const u64 kn1 = pk2(-1.f, -1.f);

    u64 mu2[2], nrstd2[2];
    #pragma unroll
    for (int p = 0; p < 2; p++) {
        u64 s01 = f2add(xp[p][0], xp[p][1]);
        u64 s23 = f2add(xp[p][2], xp[p][3]);
        u64 s45 = f2add(xp[p][4], xp[p][5]);
        u64 s67 = f2add(xp[p][6], xp[p][7]);
        u64 sum = f2add(f2add(s01,s23), f2add(s45,s67));
        u64 mu = f2mul(sum, k18);
        u64 nmu = f2mul(mu, kn1);
        u64 var = 0;
        {
            u64 d = f2add(xp[p][0], nmu); var = f2mul(d, d);
            #pragma unroll
            for (int c = 1; c < 8; c++) { d = f2add(xp[p][c], nmu); var = f2fma(d, d, var); }
        }
        var = f2mul(var, k18);
        float v0, v1; un2(var, v0, v1);
        nrstd2[p] = pk2(-rsqrtf(v0+1e-5f), -rsqrtf(v1+1e-5f));
        mu2[p] = mu;
    }

    u64 acc[2][8];
    #pragma unroll
    for (int p = 0; p < 2; p++)
        #pragma unroll
        for (int c = 0; c < 8; c++) acc[p][c] = sBO[c];

    #pragma unroll
    for (int h = 0; h < 8; h++) {
        ulonglong2 g0 = sWG[h][0], g1 = sWG[h][1], g2 = sWG[h][2], g3 = sWG[h][3];
        ulonglong2 o0 = sWO[h][0], o1 = sWO[h][1], o2 = sWO[h][2], o3 = sWO[h][3];
        u64 nw = sNW[h], cb = sCB[h];
        #pragma unroll
        for (int p = 0; p < 2; p++) {
            u64 dot = f2mul(xp[p][0], g0.x);
            dot = f2fma(xp[p][1], g0.y, dot);
            dot = f2fma(xp[p][2], g1.x, dot);
            dot = f2fma(xp[p][3], g1.y, dot);
            dot = f2fma(xp[p][4], g2.x, dot);
            dot = f2fma(xp[p][5], g2.y, dot);
            dot = f2fma(xp[p][6], g3.x, dot);
            dot = f2fma(xp[p][7], g3.y, dot);
            u64 t  = f2fma(mu2[p], nw, dot);
            u64 zn = f2fma(nrstd2[p], t, cb);
            float z0, z1; un2(zn, z0, z1);
            float t0 = __fdividef(oh[h], 1.f + __expf(z0));
            float t1 = __fdividef(oh[h], 1.f + __expf(z1));
            u64 th = pk2(t0, t1);
            acc[p][0] = f2fma(th, o0.x, acc[p][0]);
            acc[p][1] = f2fma(th, o0.y, acc[p][1]);
            acc[p][2] = f2fma(th, o1.x, acc[p][2]);
            acc[p][3] = f2fma(th, o1.y, acc[p][3]);
            acc[p][4] = f2fma(th, o2.x, acc[p][4]);
            acc[p][5] = f2fma(th, o2.y, acc[p][5]);
            acc[p][6] = f2fma(th, o3.x, acc[p][6]);
            acc[p][7] = f2fma(th, o3.y, acc[p][7]);
        }
    }

    #pragma unroll
    for (int p = 0; p < 2; p++) {
        float y0[8], y1[8];
        #pragma unroll
        for (int c = 0; c < 8; c++) un2(acc[p][c], y0[c], y1[c]);
        size_t off0 = ((size_t)(sb+2*p)*II + i)*CC;
        size_t off1 = ((size_t)(sb+2*p+1)*II + i)*CC;
        __stcs(reinterpret_cast<float4*>(out + off0),     make_float4(y0[0],y0[1],y0[2],y0[3]));
        __stcs(reinterpret_cast<float4*>(out + off0 + 4), make_float4(y0[4],y0[5],y0[6],y0[7]));
        __stcs(reinterpret_cast<float4*>(out + off1),     make_float4(y1[0],y1[1],y1[2],y1[3]));
        __stcs(reinterpret_cast<float4*>(out + off1 + 4), make_float4(y1[4],y1[5],y1[6],y1[7]));
    }
}

// ============================================================
extern "C" void kernel_launch(void* const* d_in, const int* in_sizes, int n_in,
                              void* d_out, int out_size)
{
    const float* m     = (const float*)d_in[0];
    const float* mask  = (const float*)d_in[1];
    const float* gamma = (const float*)d_in[2];
    const float* beta  = (const float*)d_in[3];
    const float* Wq    = (const float*)d_in[4];
    const float* Wk    = (const float*)d_in[5];
    const float* Wv    = (const float*)d_in[6];
    const float* Wg    = (const float*)d_in[7];
    const float* bg    = (const float*)d_in[8];
    const float* Wo    = (const float*)d_in[9];
    const float* bo    = (const float*)d_in[10];
    float* out = (float*)d_out;

    dim3 g1(II/32, SS/32);
    k1_kernel<<<g1, 256>>>(m, mask, gamma, beta, Wk, Wv);
    k2_kernel<<<II, 256>>>(Wq);
    dim3 g3(II/32, SS/32);
    k3_kernel<<<g3, 256>>>(m, gamma, beta, Wg, bg, Wo, bo, out);
}